// round 1
// baseline (speedup 1.0000x reference)
#include <cuda_runtime.h>
#include <cstdint>

// ---------------- scratch (device globals; no allocations) ----------------
__device__ float g_c1[32 * 32 * 112 * 112];   // conv1 out
__device__ float g_c2[32 * 64 * 56 * 56];     // conv2 out
__device__ float g_c3[32 * 128 * 56 * 56];    // conv3 out
__device__ float g_S [32 * 128 * 3200];       // bilinear samples S[b][c][n]
__device__ float4 g_pw[32 * 32 * 100];        // bilinear weights (wa,wb,wc,wd)
__device__ int4   g_po[32 * 32 * 100];        // gather offsets (oA,oB,oC,oD)

#define LEAK 0.2f

// ---------------- direct conv + leaky relu ----------------
// Each thread computes QC output channels (stride Cout/QC apart) x PX output
// columns. Zero padding handled by predicated loads (ir[t]=0 OOB).
template<int KS, int ST, int PD, int CIN, int QC, int PX>
__global__ void conv_leaky(const float* __restrict__ in, const float* __restrict__ wt,
                           const float* __restrict__ bias, float* __restrict__ out,
                           int Hin, int Win, int Hout, int Wout, int Cout)
{
    const int coGroups = Cout / QC;
    const int z   = blockIdx.z;
    const int bb  = z / coGroups;
    const int co0 = z % coGroups;
    const int ox0 = (blockIdx.x * blockDim.x + threadIdx.x) * PX;
    const int oy  = blockIdx.y * blockDim.y + threadIdx.y;
    if (oy >= Hout || ox0 >= Wout) return;

    float acc[QC][PX];
#pragma unroll
    for (int j = 0; j < QC; j++) {
        const float bv = bias[co0 + j * coGroups];
#pragma unroll
        for (int px = 0; px < PX; px++) acc[j][px] = bv;
    }

    const int ISPAN = (PX - 1) * ST + KS;

    for (int ci = 0; ci < CIN; ci++) {
        const float* ip = in + ((size_t)(bb * CIN + ci)) * Hin * Win;
#pragma unroll
        for (int ky = 0; ky < KS; ky++) {
            const int iy = oy * ST + ky - PD;
            if (iy < 0 || iy >= Hin) continue;

            float wr[QC][KS];
#pragma unroll
            for (int j = 0; j < QC; j++)
#pragma unroll
                for (int kx = 0; kx < KS; kx++)
                    wr[j][kx] = wt[(((size_t)(co0 + j * coGroups) * CIN + ci) * KS + ky) * KS + kx];

            float ir[ISPAN];
            const int ixb = ox0 * ST - PD;
            const float* rowp = ip + (size_t)iy * Win;
#pragma unroll
            for (int t = 0; t < ISPAN; t++) {
                const int ix = ixb + t;
                ir[t] = (ix >= 0 && ix < Win) ? rowp[ix] : 0.0f;
            }

#pragma unroll
            for (int px = 0; px < PX; px++)
#pragma unroll
                for (int kx = 0; kx < KS; kx++)
#pragma unroll
                    for (int j = 0; j < QC; j++)
                        acc[j][px] = fmaf(ir[px * ST + kx], wr[j][kx], acc[j][px]);
        }
    }

#pragma unroll
    for (int j = 0; j < QC; j++)
#pragma unroll
        for (int px = 0; px < PX; px++) {
            const int ox = ox0 + px;
            if (ox < Wout) {
                const float v = acc[j][px];
                out[(((size_t)bb * Cout + co0 + j * coGroups) * Hout + oy) * Wout + ox] =
                    v > 0.0f ? v : LEAK * v;
            }
        }
}

// ---------------- ROI coordinate / weight precompute ----------------
// One thread per (b, roi, grid point). Replicates the reference's exact
// bilinear clamp + step-clip arithmetic.
__global__ void roi_coords(const float* __restrict__ ROI)
{
    const int t = blockIdx.x * blockDim.x + threadIdx.x;
    if (t >= 32 * 32 * 100) return;
    const int b  = t / 3200;
    const int n  = t % 3200;
    const int rr = n / 100;
    const int g  = n % 100;
    const int gi = g / 10;   // row -> gy
    const int gj = g % 10;   // col -> gx

    const float* roi = ROI + ((size_t)(b * 32 + rr)) * 7;
    const float cx = roi[0], cy = roi[1];
    const float W1 = roi[2], W2 = roi[3];
    const float H1 = roi[4], H2 = roi[5];
    const float psi = roi[6];

    const float offx = ((float)gj - 4.5f) / 10.0f;
    const float offy = ((float)gi - 4.5f) / 10.0f;

    const float gx = offx * (W1 + W2) - (W1 - W2) * 0.5f;
    const float gy = offy * (H1 + H2) - (H1 - H2) * 0.5f;

    float s, c;
    sincosf(psi, &s, &c);
    // einsum with rotM = [[c,-s],[s,c]]: out0 = gx*c + gy*s; out1 = -gx*s + gy*c
    const float x = gx * c + gy * s + cx;
    const float y = -gx * s + gy * c + cy;

    const int x0i = (int)floorf(x);
    const int y0i = (int)floorf(y);
    const int x0 = min(max(x0i, 0), 55);
    const int x1 = min(max(x0i + 1, 0), 55);
    const int y0 = min(max(y0i, 0), 55);
    const int y1 = min(max(y0i + 1, 0), 55);

    const float x0f = (float)x0, x1f = (float)x1;
    const float y0f = (float)y0, y1f = (float)y1;

    float step = (x1f - x0f) * (y1f - y0f);
    step = fminf(fmaxf(step, 0.001f), 2.0f);
    const float inv = 1.0f / step;

    float4 w;
    w.x = (x1f - x) * (y1f - y) * inv;   // Ia = img[y0][x0]
    w.y = (x1f - x) * (y - y0f) * inv;   // Ib = img[y1][x0]
    w.z = (x - x0f) * (y1f - y) * inv;   // Ic = img[y0][x1]
    w.w = (x - x0f) * (y - y0f) * inv;   // Id = img[y1][x1]

    int4 o;
    o.x = y0 * 56 + x0;
    o.y = y1 * 56 + x0;
    o.z = y0 * 56 + x1;
    o.w = y1 * 56 + x1;

    g_pw[t] = w;
    g_po[t] = o;
}

// ---------------- bilinear gather: S[b][c][n] ----------------
__global__ void roi_sample()
{
    const int n = blockIdx.x * blockDim.x + threadIdx.x;
    if (n >= 3200) return;
    const int c = blockIdx.y;
    const int b = blockIdx.z;

    const float4 w = g_pw[b * 3200 + n];
    const int4   o = g_po[b * 3200 + n];
    const float* feat = g_c3 + ((size_t)(b * 128 + c)) * 3136;

    const float v = feat[o.x] * w.x + feat[o.y] * w.y + feat[o.z] * w.z + feat[o.w] * w.w;
    g_S[((size_t)(b * 128 + c)) * 3200 + n] = v;
}

// ---------------- FC: out = S(1024x12800) @ fc_w^T(12800x256) + fc_b ----------------
__global__ void fc_init(float* __restrict__ out, const float* __restrict__ fc_b)
{
    const int t = blockIdx.x * blockDim.x + threadIdx.x;
    if (t < 1024 * 256) out[t] = fc_b[t & 255];
}

// 64x64 output tile, BK=16, 256 threads, 4x4 per thread. K split across
// blockIdx.z (4 slices of 3200) accumulated via atomicAdd.
__global__ void fc_gemm(const float* __restrict__ W, float* __restrict__ out)
{
    __shared__ float As[16][68];
    __shared__ float Bs[16][68];

    const float* A = g_S;              // (1024, 12800) row-major view
    const int n0  = blockIdx.x * 64;
    const int m0  = blockIdx.y * 64;
    const int kb0 = blockIdx.z * 3200;

    const int tid = threadIdx.x;
    const int ldr   = tid >> 2;          // 0..63 (row for A, col n for W)
    const int lane4 = (tid & 3) * 4;     // k offset 0,4,8,12
    const int tr = tid >> 4;             // 0..15
    const int tc = tid & 15;             // 0..15

    float acc[4][4];
#pragma unroll
    for (int i = 0; i < 4; i++)
#pragma unroll
        for (int j = 0; j < 4; j++) acc[i][j] = 0.0f;

    for (int kb = kb0; kb < kb0 + 3200; kb += 16) {
        const float4 a4 = *(const float4*)(A + (size_t)(m0 + ldr) * 12800 + kb + lane4);
        const float4 b4 = *(const float4*)(W + (size_t)(n0 + ldr) * 12800 + kb + lane4);
        As[lane4 + 0][ldr] = a4.x;  As[lane4 + 1][ldr] = a4.y;
        As[lane4 + 2][ldr] = a4.z;  As[lane4 + 3][ldr] = a4.w;
        Bs[lane4 + 0][ldr] = b4.x;  Bs[lane4 + 1][ldr] = b4.y;
        Bs[lane4 + 2][ldr] = b4.z;  Bs[lane4 + 3][ldr] = b4.w;
        __syncthreads();

#pragma unroll
        for (int kk = 0; kk < 16; kk++) {
            float av[4], bv[4];
#pragma unroll
            for (int i = 0; i < 4; i++) av[i] = As[kk][tr * 4 + i];
#pragma unroll
            for (int j = 0; j < 4; j++) bv[j] = Bs[kk][tc * 4 + j];
#pragma unroll
            for (int i = 0; i < 4; i++)
#pragma unroll
                for (int j = 0; j < 4; j++)
                    acc[i][j] = fmaf(av[i], bv[j], acc[i][j]);
        }
        __syncthreads();
    }

#pragma unroll
    for (int i = 0; i < 4; i++)
#pragma unroll
        for (int j = 0; j < 4; j++)
            atomicAdd(out + (size_t)(m0 + tr * 4 + i) * 256 + n0 + tc * 4 + j, acc[i][j]);
}

// ---------------- launch ----------------
extern "C" void kernel_launch(void* const* d_in, const int* in_sizes, int n_in,
                              void* d_out, int out_size)
{
    const float* x    = (const float*)d_in[0];
    const float* ROI  = (const float*)d_in[1];
    const float* w1   = (const float*)d_in[2];
    const float* b1   = (const float*)d_in[3];
    const float* w2   = (const float*)d_in[4];
    const float* b2   = (const float*)d_in[5];
    const float* w3   = (const float*)d_in[6];
    const float* b3   = (const float*)d_in[7];
    const float* fc_w = (const float*)d_in[8];
    const float* fc_b = (const float*)d_in[9];
    float* out = (float*)d_out;

    float *p_c1, *p_c2, *p_c3;
    cudaGetSymbolAddress((void**)&p_c1, g_c1);
    cudaGetSymbolAddress((void**)&p_c2, g_c2);
    cudaGetSymbolAddress((void**)&p_c3, g_c3);

    // conv1: 3 -> 32, 5x5 s2 p2, 224 -> 112
    conv_leaky<5, 2, 2, 3, 2, 4><<<dim3(1, 14, 32 * 16), dim3(28, 8)>>>(
        x, w1, b1, p_c1, 224, 224, 112, 112, 32);

    // conv2: 32 -> 64, 5x5 s2 p2, 112 -> 56
    conv_leaky<5, 2, 2, 32, 4, 4><<<dim3(1, 4, 32 * 16), dim3(14, 16)>>>(
        p_c1, w2, b2, p_c2, 112, 112, 56, 56, 64);

    // conv3: 64 -> 128, 3x3 s1 p1, 56 -> 56
    conv_leaky<3, 1, 1, 64, 4, 4><<<dim3(1, 4, 32 * 32), dim3(14, 16)>>>(
        p_c2, w3, b3, p_c3, 56, 56, 56, 56, 128);

    // ROI sampling
    roi_coords<<<(32 * 32 * 100 + 255) / 256, 256>>>(ROI);
    roi_sample<<<dim3(13, 128, 32), 256>>>();

    // FC
    fc_init<<<1024, 256>>>(out, fc_b);
    fc_gemm<<<dim3(4, 16, 4), 256>>>(fc_w, out);
}

// round 3
// speedup vs baseline: 1.6764x; 1.6764x over previous
#include <cuda_runtime.h>
#include <cstdint>

typedef unsigned long long ull;

// ---------------- scratch (device globals) ----------------
__device__ float g_c1[32 * 32 * 112 * 112];     // conv1 out, NCHW
__device__ float g_c2[32 * 64 * 56 * 56];       // conv2 out, NCHW
__device__ float g_c3[32 * 56 * 56 * 128];      // conv3 out, channels-LAST [b][y][x][c]
__device__ float g_S [32 * 128 * 3200];         // samples in samp memory order: [b][c][n]
__device__ float4 g_pw[32 * 32 * 100];          // bilinear weights
__device__ int4   g_po[32 * 32 * 100];          // corner offsets (channels-last, pre-scaled by 128)

#define LEAK 0.2f

// ---------------- f32x2 helpers ----------------
__device__ __forceinline__ ull pack2(float lo, float hi) {
    ull r; asm("mov.b64 %0, {%1, %2};" : "=l"(r) : "f"(lo), "f"(hi)); return r;
}
__device__ __forceinline__ void unpack2(ull v, float& lo, float& hi) {
    asm("mov.b64 {%0, %1}, %2;" : "=f"(lo), "=f"(hi) : "l"(v));
}
__device__ __forceinline__ ull ffma2(ull a, ull b, ull c) {
    ull d; asm("fma.rn.f32x2 %0, %1, %2, %3;" : "=l"(d) : "l"(a), "l"(b), "l"(c)); return d;
}

// ---------------- conv + leaky, FFMA2 over channel pairs ----------------
template<int KS, int ST, int PD, int CIN, int QC, int PX, bool CLAST>
__global__ void conv_leaky(const float* __restrict__ in, const float* __restrict__ wt,
                           const float* __restrict__ bias, float* __restrict__ out,
                           int Hin, int Win, int Hout, int Wout, int Cout)
{
    constexpr int KK = KS * KS;
    constexpr int ISPAN = (PX - 1) * ST + KS;
    constexpr int JP = QC / 2;

    __shared__ float ws[CIN * KK * QC];

    const int coGroups = Cout / QC;
    const int z  = blockIdx.z;
    const int bb = z / coGroups;
    const int cb = (z % coGroups) * QC;   // contiguous channel base

    for (int idx = threadIdx.y * blockDim.x + threadIdx.x;
         idx < CIN * KK * QC; idx += blockDim.x * blockDim.y) {
        const int j    = idx & (QC - 1);
        const int rest = idx / QC;
        const int k    = rest % KK;
        const int ci   = rest / KK;
        ws[idx] = wt[((size_t)(cb + j) * CIN + ci) * KK + k];
    }
    __syncthreads();

    const int ox0 = (blockIdx.x * blockDim.x + threadIdx.x) * PX;
    const int oy  = blockIdx.y * blockDim.y + threadIdx.y;

    ull acc[JP][PX];
#pragma unroll
    for (int jp = 0; jp < JP; jp++) {
        const ull bv = pack2(bias[cb + 2 * jp], bias[cb + 2 * jp + 1]);
#pragma unroll
        for (int px = 0; px < PX; px++) acc[jp][px] = bv;
    }

    const int ixb = ox0 * ST - PD;

    for (int ci = 0; ci < CIN; ci++) {
        const float* ip = in + ((size_t)(bb * CIN + ci)) * Hin * Win;
#pragma unroll
        for (int ky = 0; ky < KS; ky++) {
            const int iy = oy * ST + ky - PD;
            if (iy < 0 || iy >= Hin) continue;
            const float* rowp = ip + (size_t)iy * Win;

            ull bp[ISPAN];
#pragma unroll
            for (int t = 0; t < ISPAN; t++) {
                const int ix = ixb + t;
                const float v = (ix >= 0 && ix < Win) ? rowp[ix] : 0.0f;
                bp[t] = pack2(v, v);
            }

            const float* wrow = ws + (ci * KK + ky * KS) * QC;
#pragma unroll
            for (int kx = 0; kx < KS; kx++) {
                ull w[JP];
#pragma unroll
                for (int jp = 0; jp < JP; jp++)
                    w[jp] = *(const ull*)(wrow + kx * QC + 2 * jp);
#pragma unroll
                for (int px = 0; px < PX; px++) {
                    const ull b2 = bp[px * ST + kx];
#pragma unroll
                    for (int jp = 0; jp < JP; jp++)
                        acc[jp][px] = ffma2(w[jp], b2, acc[jp][px]);
                }
            }
        }
    }

#pragma unroll
    for (int jp = 0; jp < JP; jp++)
#pragma unroll
        for (int px = 0; px < PX; px++) {
            float lo, hi; unpack2(acc[jp][px], lo, hi);
            lo = lo > 0.0f ? lo : LEAK * lo;
            hi = hi > 0.0f ? hi : LEAK * hi;
            const int ox = ox0 + px;
            if (CLAST) {
                float2 v2 = make_float2(lo, hi);
                *(float2*)(out + (((size_t)(bb * Hout + oy) * Wout + ox) * Cout) + cb + 2 * jp) = v2;
            } else {
                out[((size_t)(bb * Cout + cb + 2 * jp) * Hout + oy) * Wout + ox] = lo;
                out[((size_t)(bb * Cout + cb + 2 * jp + 1) * Hout + oy) * Wout + ox] = hi;
            }
        }
}

// ---------------- ROI coordinate / weight precompute ----------------
__global__ void roi_coords(const float* __restrict__ ROI)
{
    const int t = blockIdx.x * blockDim.x + threadIdx.x;
    if (t >= 32 * 32 * 100) return;
    const int b  = t / 3200;
    const int n  = t % 3200;
    const int rr = n / 100;
    const int g  = n % 100;
    const int gi = g / 10;
    const int gj = g % 10;

    const float* roi = ROI + ((size_t)(b * 32 + rr)) * 7;
    const float cx = roi[0], cy = roi[1];
    const float W1 = roi[2], W2 = roi[3];
    const float H1 = roi[4], H2 = roi[5];
    const float psi = roi[6];

    const float offx = ((float)gj - 4.5f) / 10.0f;
    const float offy = ((float)gi - 4.5f) / 10.0f;

    const float gx = offx * (W1 + W2) - (W1 - W2) * 0.5f;
    const float gy = offy * (H1 + H2) - (H1 - H2) * 0.5f;

    float s, c;
    sincosf(psi, &s, &c);
    const float x = gx * c + gy * s + cx;
    const float y = -gx * s + gy * c + cy;

    const int x0i = (int)floorf(x);
    const int y0i = (int)floorf(y);
    const int x0 = min(max(x0i, 0), 55);
    const int x1 = min(max(x0i + 1, 0), 55);
    const int y0 = min(max(y0i, 0), 55);
    const int y1 = min(max(y0i + 1, 0), 55);

    const float x0f = (float)x0, x1f = (float)x1;
    const float y0f = (float)y0, y1f = (float)y1;

    float step = (x1f - x0f) * (y1f - y0f);
    step = fminf(fmaxf(step, 0.001f), 2.0f);
    const float inv = 1.0f / step;

    float4 w;
    w.x = (x1f - x) * (y1f - y) * inv;
    w.y = (x1f - x) * (y - y0f) * inv;
    w.z = (x - x0f) * (y1f - y) * inv;
    w.w = (x - x0f) * (y - y0f) * inv;

    int4 o;  // channels-last offsets
    o.x = (y0 * 56 + x0) * 128;
    o.y = (y1 * 56 + x0) * 128;
    o.z = (y0 * 56 + x1) * 128;
    o.w = (y1 * 56 + x1) * 128;

    g_pw[t] = w;
    g_po[t] = o;
}

// ---------------- bilinear sample ----------------
// Phase 1: warp y handles point n = n0+y; lane cq covers channels 4cq..4cq+3
//          (coalesced 512B corner loads from channels-last conv3). Result to smem.
// Phase 2: transpose out of smem so stores into g_S[b][c][n] are coalesced.
__global__ void roi_sample()
{
    __shared__ float sm[32][132];     // [n within tile][channel], padded

    const int b  = blockIdx.y;
    const int n0 = blockIdx.x * 32;
    const int cq = threadIdx.x;       // 0..31
    const int y  = threadIdx.y;       // 0..31
    const int n  = n0 + y;

    const float4 w = g_pw[b * 3200 + n];
    const int4   o = g_po[b * 3200 + n];
    const float* feat = g_c3 + (size_t)b * 56 * 56 * 128;

    const float4 A = *(const float4*)(feat + o.x + cq * 4);
    const float4 B = *(const float4*)(feat + o.y + cq * 4);
    const float4 C = *(const float4*)(feat + o.z + cq * 4);
    const float4 D = *(const float4*)(feat + o.w + cq * 4);

    float4 r;
    r.x = A.x * w.x + B.x * w.y + C.x * w.z + D.x * w.w;
    r.y = A.y * w.x + B.y * w.y + C.y * w.z + D.y * w.w;
    r.z = A.z * w.x + B.z * w.y + C.z * w.z + D.z * w.w;
    r.w = A.w * w.x + B.w * w.y + C.w * w.z + D.w * w.w;

    *(float4*)&sm[y][cq * 4] = r;
    __syncthreads();

    // transpose writeout: thread -> channel c = tid/8, n-quad nq = tid%8
    const int tid = y * 32 + cq;
    const int c   = tid >> 3;
    const int nq  = tid & 7;
    float4 v;
    v.x = sm[nq * 4 + 0][c];
    v.y = sm[nq * 4 + 1][c];
    v.z = sm[nq * 4 + 2][c];
    v.w = sm[nq * 4 + 3][c];
    *(float4*)(g_S + ((size_t)(b * 128 + c)) * 3200 + n0 + nq * 4) = v;
}

// ---------------- FC ----------------
__global__ void fc_init(float* __restrict__ out, const float* __restrict__ fc_b)
{
    const int t = blockIdx.x * blockDim.x + threadIdx.x;
    if (t < 1024 * 256) out[t] = fc_b[t & 255];
}

// 64x64 tile, BK=16, 256 threads, 4x4/thread, K split 8-way via atomicAdd.
// A = g_S viewed (1024 x 12800): row (b*32+r) is a contiguous 12800-slice,
// which is EXACTLY the reference's buggy reshape memory order. W = fc_w as-is.
__global__ void fc_gemm(const float* __restrict__ W, float* __restrict__ out)
{
    __shared__ __align__(16) float As[16][68];
    __shared__ __align__(16) float Bs[16][68];

    const float* A = g_S;
    const int n0  = blockIdx.x * 64;
    const int m0  = blockIdx.y * 64;
    const int kb0 = blockIdx.z * 1600;

    const int tid   = threadIdx.x;
    const int ldr   = tid >> 2;
    const int lane4 = (tid & 3) * 4;
    const int tr = tid >> 4;
    const int tc = tid & 15;

    float acc[4][4];
#pragma unroll
    for (int i = 0; i < 4; i++)
#pragma unroll
        for (int j = 0; j < 4; j++) acc[i][j] = 0.0f;

    for (int kb = kb0; kb < kb0 + 1600; kb += 16) {
        const float4 a4 = *(const float4*)(A + (size_t)(m0 + ldr) * 12800 + kb + lane4);
        const float4 b4 = *(const float4*)(W + (size_t)(n0 + ldr) * 12800 + kb + lane4);
        As[lane4 + 0][ldr] = a4.x;  As[lane4 + 1][ldr] = a4.y;
        As[lane4 + 2][ldr] = a4.z;  As[lane4 + 3][ldr] = a4.w;
        Bs[lane4 + 0][ldr] = b4.x;  Bs[lane4 + 1][ldr] = b4.y;
        Bs[lane4 + 2][ldr] = b4.z;  Bs[lane4 + 3][ldr] = b4.w;
        __syncthreads();

#pragma unroll
        for (int kk = 0; kk < 16; kk++) {
            const float4 av = *(const float4*)&As[kk][tr * 4];
            const float4 bv = *(const float4*)&Bs[kk][tc * 4];
            acc[0][0] = fmaf(av.x, bv.x, acc[0][0]);
            acc[0][1] = fmaf(av.x, bv.y, acc[0][1]);
            acc[0][2] = fmaf(av.x, bv.z, acc[0][2]);
            acc[0][3] = fmaf(av.x, bv.w, acc[0][3]);
            acc[1][0] = fmaf(av.y, bv.x, acc[1][0]);
            acc[1][1] = fmaf(av.y, bv.y, acc[1][1]);
            acc[1][2] = fmaf(av.y, bv.z, acc[1][2]);
            acc[1][3] = fmaf(av.y, bv.w, acc[1][3]);
            acc[2][0] = fmaf(av.z, bv.x, acc[2][0]);
            acc[2][1] = fmaf(av.z, bv.y, acc[2][1]);
            acc[2][2] = fmaf(av.z, bv.z, acc[2][2]);
            acc[2][3] = fmaf(av.z, bv.w, acc[2][3]);
            acc[3][0] = fmaf(av.w, bv.x, acc[3][0]);
            acc[3][1] = fmaf(av.w, bv.y, acc[3][1]);
            acc[3][2] = fmaf(av.w, bv.z, acc[3][2]);
            acc[3][3] = fmaf(av.w, bv.w, acc[3][3]);
        }
        __syncthreads();
    }

#pragma unroll
    for (int i = 0; i < 4; i++)
#pragma unroll
        for (int j = 0; j < 4; j++)
            atomicAdd(out + (size_t)(m0 + tr * 4 + i) * 256 + n0 + tc * 4 + j, acc[i][j]);
}

// ---------------- launch ----------------
extern "C" void kernel_launch(void* const* d_in, const int* in_sizes, int n_in,
                              void* d_out, int out_size)
{
    const float* x    = (const float*)d_in[0];
    const float* ROI  = (const float*)d_in[1];
    const float* w1   = (const float*)d_in[2];
    const float* b1   = (const float*)d_in[3];
    const float* w2   = (const float*)d_in[4];
    const float* b2   = (const float*)d_in[5];
    const float* w3   = (const float*)d_in[6];
    const float* b3   = (const float*)d_in[7];
    const float* fc_w = (const float*)d_in[8];
    const float* fc_b = (const float*)d_in[9];
    float* out = (float*)d_out;

    float *p_c1, *p_c2, *p_c3;
    cudaGetSymbolAddress((void**)&p_c1, g_c1);
    cudaGetSymbolAddress((void**)&p_c2, g_c2);
    cudaGetSymbolAddress((void**)&p_c3, g_c3);

    roi_coords<<<(32 * 32 * 100 + 255) / 256, 256>>>(ROI);

    // conv1: 3 -> 32, 5x5 s2 p2, 224 -> 112 (NCHW out)
    conv_leaky<5, 2, 2, 3, 8, 4, false><<<dim3(1, 28, 32 * 4), dim3(28, 4)>>>(
        x, w1, b1, p_c1, 224, 224, 112, 112, 32);

    // conv2: 32 -> 64, 5x5 s2 p2, 112 -> 56 (NCHW out)
    conv_leaky<5, 2, 2, 32, 8, 4, false><<<dim3(1, 7, 32 * 8), dim3(14, 8)>>>(
        p_c1, w2, b2, p_c2, 112, 112, 56, 56, 64);

    // conv3: 64 -> 128, 3x3 s1 p1, 56 -> 56 (channels-LAST out)
    conv_leaky<3, 1, 1, 64, 8, 4, true><<<dim3(1, 7, 32 * 16), dim3(14, 8)>>>(
        p_c2, w3, b3, p_c3, 56, 56, 56, 56, 128);

    // sampling: block covers 32 points x 128 channels, smem transpose for stores
    roi_sample<<<dim3(100, 32), dim3(32, 32)>>>();

    // FC
    fc_init<<<1024, 256>>>(out, fc_b);
    fc_gemm<<<dim3(4, 16, 8), 256>>>(fc_w, out);
}